// round 17
// baseline (speedup 1.0000x reference)
#include <cuda_runtime.h>
#include <math_constants.h>

// Problem shapes (from reference setup_inputs)
#define B_DIM 8
#define C_IN 32
#define C_OUT 32
#define P_DIM 262144
#define K_SH 81                         // (MAX_L+1)^2, MAX_L=8
#define N_ROWS (B_DIM * C_IN)           // 256
#define SPLITS 4
#define CHUNK (P_DIM / SPLITS)          // 65536 elements per block (256 KB)
#define THREADS 256
#define N_RED_BLOCKS (N_ROWS * SPLITS)  // 1024

// Scratch (no cudaMalloc allowed). g_done starts 0; last block resets it
// before exiting, so the correctness run and every graph replay start clean.
__device__ float g_partials[N_RED_BLOCKS];
__device__ int   g_done;

// ---------------------------------------------------------------------------
// Cold epilogue, executed by EXACTLY ONE block (the last to finish).
// __noinline__ is the register firewall: its register demand must not
// inflate the streaming path's allocation (the R12 failure mode).
// Minimal smem (1 KB) so block occupancy of the streaming wave is untouched.
// ---------------------------------------------------------------------------
__device__ __noinline__ void last_block_tail(
        const float* __restrict__ coeff, float* __restrict__ out) {
    __shared__ float s_rows[N_ROWS];

    // Fold SPLITS partials per row: thread t -> row t (L2-hit float4 load).
    {
        float4 pp = reinterpret_cast<const float4*>(g_partials)[threadIdx.x];
        s_rows[threadIdx.x] = (pp.x + pp.y) + (pp.z + pp.w);
    }
    __syncthreads();

    // Thread t owns output row (b, o): writes all 81 k-slots.
    const int b = threadIdx.x / C_OUT;
    const int o = threadIdx.x % C_OUT;
    float* orow = out + (size_t)threadIdx.x * K_SH;
    const float* srow = &s_rows[b * C_IN];
    const float* crow = coeff + (size_t)o * C_IN * K_SH;   // coeff[o, :, :]

    // Zeros for the 72 m != 0 slots.
    #pragma unroll
    for (int k = 0; k < K_SH; ++k)
        orow[k] = 0.0f;

    // 9 m == 0 slots: out[b,o,l*l+l] = Y_l * sum_i coeff[o,i,k] * s[b,i].
    // coeff loads: 32 independent per l (ILP); rows with the same o across
    // the 8 b's hit L2/L1 after first touch.
    #pragma unroll
    for (int l = 0; l < 9; ++l) {
        const int k = l * l + l;
        const float y = sqrtf((2.0f * l + 1.0f) / (4.0f * CUDART_PI_F));
        float acc = 0.0f;
        #pragma unroll
        for (int i = 0; i < C_IN; ++i)
            acc += crow[(size_t)i * K_SH + k] * srow[i];
        orow[k] = y * acc;
    }
}

// ---------------------------------------------------------------------------
// Fused kernel: streaming reduce (byte-identical hot path to the R11
// champion: natural registers, no min-blocks bound, __ldcs) + last-block
// epilogue. No second grid, no PDL, no handoff.
// ---------------------------------------------------------------------------
__global__ void __launch_bounds__(THREADS) fused_kernel(
        const float* __restrict__ in,
        const float* __restrict__ coeff,
        float* __restrict__ out) {

    const int row   = blockIdx.x / SPLITS;
    const int split = blockIdx.x % SPLITS;
    const float4* __restrict__ p =
        reinterpret_cast<const float4*>(in + (size_t)row * P_DIM + (size_t)split * CHUNK);

    float a0 = 0.f, a1 = 0.f, a2 = 0.f, a3 = 0.f;
    #pragma unroll 4
    for (int jo = 0; jo < 16; ++jo) {
        float4 v0 = __ldcs(&p[threadIdx.x + (jo * 4 + 0) * THREADS]);
        float4 v1 = __ldcs(&p[threadIdx.x + (jo * 4 + 1) * THREADS]);
        float4 v2 = __ldcs(&p[threadIdx.x + (jo * 4 + 2) * THREADS]);
        float4 v3 = __ldcs(&p[threadIdx.x + (jo * 4 + 3) * THREADS]);
        a0 += (v0.x + v0.y) + (v0.z + v0.w);
        a1 += (v1.x + v1.y) + (v1.z + v1.w);
        a2 += (v2.x + v2.y) + (v2.z + v2.w);
        a3 += (v3.x + v3.y) + (v3.z + v3.w);
    }
    float acc = (a0 + a1) + (a2 + a3);

    #pragma unroll
    for (int off = 16; off > 0; off >>= 1)
        acc += __shfl_xor_sync(0xFFFFFFFFu, acc, off);

    __shared__ float warp_sums[THREADS / 32];
    const int lane = threadIdx.x & 31;
    const int wid  = threadIdx.x >> 5;
    if (lane == 0) warp_sums[wid] = acc;
    __syncthreads();

    if (wid == 0) {
        float s = (lane < THREADS / 32) ? warp_sums[lane] : 0.0f;
        #pragma unroll
        for (int off = 4; off > 0; off >>= 1)
            s += __shfl_xor_sync(0xFFFFFFFFu, s, off);
        if (lane == 0) g_partials[blockIdx.x] = s;
    }

    // Last-block election (no waiting: exactly one block sees old == 1023).
    __shared__ int s_is_last;
    if (threadIdx.x == 0) {
        __threadfence();                       // release this block's partial
        s_is_last = (atomicAdd(&g_done, 1) == N_RED_BLOCKS - 1);
    }
    __syncthreads();
    if (!s_is_last) return;
    __threadfence();                           // acquire all partials

    last_block_tail(coeff, out);

    // Reset for the next replay (single writer; all other blocks returned).
    __syncthreads();
    if (threadIdx.x == 0) g_done = 0;
}

// ---------------------------------------------------------------------------
extern "C" void kernel_launch(void* const* d_in, const int* in_sizes, int n_in,
                              void* d_out, int out_size) {
    const float* input = (const float*)d_in[0];   // [B, C_in, P]
    const float* coeff = (const float*)d_in[1];   // [C_out, C_in, K]
    float* out = (float*)d_out;                   // [B, C_out, K]

    fused_kernel<<<N_RED_BLOCKS, THREADS>>>(input, coeff, out);
}